// round 6
// baseline (speedup 1.0000x reference)
#include <cuda_runtime.h>
#include <math.h>

#define C_   16
#define I_   64
#define H_   40
#define T_   512
#define G_   120
#define GP   128
#define TCH  4

typedef unsigned long long u64;

// 1 GB scratch: gi[b][c][t][g] with g-rows of 120 floats (includes b_ih)
__device__ float g_gi[(size_t)256 * 16 * 512 * 120];

__device__ __forceinline__ u64 pack2(float lo, float hi) {
    u64 r;
    asm("mov.b64 %0, {%1, %2};"
        : "=l"(r) : "r"(__float_as_uint(lo)), "r"(__float_as_uint(hi)));
    return r;
}
__device__ __forceinline__ u64 dup2(float v) {
    u64 r;
    asm("mov.b64 %0, {%1, %1};" : "=l"(r) : "r"(__float_as_uint(v)));
    return r;
}
__device__ __forceinline__ u64 fma2(u64 a, u64 b, u64 c) {
    u64 d;
    asm("fma.rn.f32x2 %0, %1, %2, %3;" : "=l"(d) : "l"(a), "l"(b), "l"(c));
    return d;
}
__device__ __forceinline__ void unpack2(u64 v, float& lo, float& hi) {
    unsigned a, b;
    asm("mov.b64 {%0, %1}, %2;" : "=r"(a), "=r"(b) : "l"(v));
    lo = __uint_as_float(a); hi = __uint_as_float(b);
}
__device__ __forceinline__ float sigf(float v) {
    return __fdividef(1.0f, 1.0f + __expf(-v));
}
__device__ __forceinline__ float tanh_fast(float a) {
    a = fminf(fmaxf(a, -15.0f), 15.0f);
    float e = __expf(2.0f * a);
    return __fdividef(e - 1.0f, e + 1.0f);
}

// ============================================================================
// Kernel 1: gi[b,c,t,:] = W_ih[c] . x[b,c,:,t] + b_ih[c]   (parallel GEMM)
// CTA = (c, 16-batch block), 128 threads, TCH=4 timesteps/chunk.
// ============================================================================
#define K1_BN 16
#define K1_WIH 0                             // [64][128]
#define K1_X   (K1_WIH + I_ * GP)            // [4][64][16]
#define K1_TOT (K1_X + TCH * I_ * K1_BN)     // 12288 floats = 49152 B

__global__ void __launch_bounds__(128, 2)
gi_gemm_kernel(const float* __restrict__ x,
               const float* __restrict__ Wih,
               const float* __restrict__ bih)
{
    extern __shared__ float sm[];
    const int tid = threadIdx.x;
    const int c   = blockIdx.x & 15;
    const int b0  = (blockIdx.x >> 4) * K1_BN;

    for (int p = tid; p < I_ * GP; p += 128) {
        int k = p >> 7, g = p & 127;
        sm[K1_WIH + p] = (g < G_) ? Wih[(c * G_ + g) * I_ + k] : 0.0f;
    }
    __syncthreads();

    const int wid = tid >> 5;
    const int gt  = tid & 31;

    const int g0 = 2 * gt, g1 = 64 + 2 * gt;
    float bi1a = (g1     < G_) ? bih[c * G_ + g1]     : 0.0f;
    float bi1b = (g1 + 1 < G_) ? bih[c * G_ + g1 + 1] : 0.0f;
    const u64 bI0 = pack2(bih[c * G_ + g0], bih[c * G_ + g0 + 1]);
    const u64 bI1 = pack2(bi1a, bi1b);

    const float* wI = sm + K1_WIH + 2 * gt;

    const int lb  = tid & 15;
    const int lig = tid >> 4;
    const float* xg = x + ((size_t)(b0 + lb) * C_ + c) * (size_t)(I_ * T_);

    for (int tc = 0; tc < T_; tc += TCH) {
        __syncthreads();
        #pragma unroll
        for (int r = 0; r < 8; ++r) {
            int i = lig + (r << 3);
            float4 v = *(const float4*)(xg + i * T_ + tc);
            float* xp = sm + K1_X + i * 16 + lb;    // tt stride = 1024
            xp[0] = v.x; xp[1024] = v.y; xp[2048] = v.z; xp[3072] = v.w;
        }
        __syncthreads();

        // warp wid computes tt = wid for all 16 batches
        u64 a0[16], a1[16];
        #pragma unroll
        for (int b = 0; b < 16; ++b) { a0[b] = bI0; a1[b] = bI1; }
        const float* xr = sm + K1_X + wid * 1024;
        #pragma unroll 4
        for (int k = 0; k < I_; ++k) {
            u64 w0 = *(const u64*)(wI + k * GP);
            u64 w1 = *(const u64*)(wI + k * GP + 64);
            const float* xk = xr + k * 16;
            float4 xa = *(const float4*)(xk);
            float4 xb = *(const float4*)(xk + 4);
            float4 xc = *(const float4*)(xk + 8);
            float4 xd = *(const float4*)(xk + 12);
            u64 d0 = dup2(xa.x), d1 = dup2(xa.y), d2 = dup2(xa.z), d3 = dup2(xa.w);
            u64 d4 = dup2(xb.x), d5 = dup2(xb.y), d6 = dup2(xb.z), d7 = dup2(xb.w);
            u64 d8 = dup2(xc.x), d9 = dup2(xc.y), da = dup2(xc.z), db = dup2(xc.w);
            u64 dc = dup2(xd.x), dd = dup2(xd.y), de = dup2(xd.z), df = dup2(xd.w);
            a0[0]  = fma2(w0, d0, a0[0]);  a1[0]  = fma2(w1, d0, a1[0]);
            a0[1]  = fma2(w0, d1, a0[1]);  a1[1]  = fma2(w1, d1, a1[1]);
            a0[2]  = fma2(w0, d2, a0[2]);  a1[2]  = fma2(w1, d2, a1[2]);
            a0[3]  = fma2(w0, d3, a0[3]);  a1[3]  = fma2(w1, d3, a1[3]);
            a0[4]  = fma2(w0, d4, a0[4]);  a1[4]  = fma2(w1, d4, a1[4]);
            a0[5]  = fma2(w0, d5, a0[5]);  a1[5]  = fma2(w1, d5, a1[5]);
            a0[6]  = fma2(w0, d6, a0[6]);  a1[6]  = fma2(w1, d6, a1[6]);
            a0[7]  = fma2(w0, d7, a0[7]);  a1[7]  = fma2(w1, d7, a1[7]);
            a0[8]  = fma2(w0, d8, a0[8]);  a1[8]  = fma2(w1, d8, a1[8]);
            a0[9]  = fma2(w0, d9, a0[9]);  a1[9]  = fma2(w1, d9, a1[9]);
            a0[10] = fma2(w0, da, a0[10]); a1[10] = fma2(w1, da, a1[10]);
            a0[11] = fma2(w0, db, a0[11]); a1[11] = fma2(w1, db, a1[11]);
            a0[12] = fma2(w0, dc, a0[12]); a1[12] = fma2(w1, dc, a1[12]);
            a0[13] = fma2(w0, dd, a0[13]); a1[13] = fma2(w1, dd, a1[13]);
            a0[14] = fma2(w0, de, a0[14]); a1[14] = fma2(w1, de, a1[14]);
            a0[15] = fma2(w0, df, a0[15]); a1[15] = fma2(w1, df, a1[15]);
        }
        const int t = tc + wid;
        #pragma unroll
        for (int b = 0; b < 16; ++b) {
            float* gp = g_gi + (((size_t)(b0 + b) * C_ + c) * T_ + t) * G_;
            *(u64*)(gp + 2 * gt) = a0[b];
            if (gt < 28) *(u64*)(gp + 64 + 2 * gt) = a1[b];
        }
    }
}

// ============================================================================
// Kernel 2: recurrence. grid 512 = (c, 8-batch block). Warp owns 2 batches,
// all gates. No block barriers in the T loop. gi via warp-local cp.async.
// ============================================================================
#define K2_BN 8
#define HS2   10
#define PRS2  132
#define K2_WHH 0                              // [40][128]
#define K2_H   (K2_WHH + H_ * GP)             // [40][10]
#define K2_GH  (K2_H + H_ * HS2)              // [8][132]
#define K2_GIB (K2_GH + K2_BN * PRS2)         // [4 warps][2 buf][2 b][120]
#define K2_TOT (K2_GIB + 4 * 2 * 2 * G_)      // 8496 floats = 33984 B

__device__ __forceinline__ void cp16(unsigned smem_addr, const void* gptr) {
    asm volatile("cp.async.ca.shared.global [%0], [%1], 16;"
                 :: "r"(smem_addr), "l"(gptr));
}

__global__ void __launch_bounds__(128)
gru_rec_kernel(const float* __restrict__ Whh,
               const float* __restrict__ bhh,
               const float* __restrict__ Wfc,
               const float* __restrict__ bfc,
               float* __restrict__ out)
{
    extern __shared__ float sm[];
    const int tid = threadIdx.x;
    const int c   = blockIdx.x & 15;
    const int b0  = (blockIdx.x >> 4) * K2_BN;

    for (int p = tid; p < H_ * GP; p += 128) {
        int k = p >> 7, g = p & 127;
        sm[K2_WHH + p] = (g < G_) ? Whh[(c * G_ + g) * H_ + k] : 0.0f;
    }
    for (int p = tid; p < H_ * HS2; p += 128) sm[K2_H + p] = 0.0f;
    __syncthreads();

    const int wid = tid >> 5;
    const int gt  = tid & 31;

    const int g0 = 2 * gt, g1 = 64 + 2 * gt;
    float bh1a = (g1     < G_) ? bhh[c * G_ + g1]     : 0.0f;
    float bh1b = (g1 + 1 < G_) ? bhh[c * G_ + g1 + 1] : 0.0f;
    const u64 bH0 = pack2(bhh[c * G_ + g0], bhh[c * G_ + g0 + 1]);
    const u64 bH1 = pack2(bh1a, bh1b);

    const float* wH = sm + K2_WHH + 2 * gt;

    // warp-local gi prefetch: 2 batches x 120 floats = 60 x 16B chunks
    const unsigned gib_base =
        (unsigned)__cvta_generic_to_shared(sm + K2_GIB + wid * 480);
    const int ch0 = gt;           // chunk indices: gt and gt+32 (if < 60)
    const int b_of0 = ch0 / 30, o_of0 = ch0 % 30;
    const int ch1 = gt + 32;
    const int b_of1 = ch1 / 30, o_of1 = ch1 % 30;
    const size_t gi_row0 =
        ((size_t)(b0 + wid * 2 + b_of0) * C_ + c) * T_;   // + t, then *G_
    const size_t gi_row1 =
        ((size_t)(b0 + wid * 2 + b_of1) * C_ + c) * T_;

    // prefetch t = 0 into buf 0
    {
        cp16(gib_base + (unsigned)(b_of0 * G_ + o_of0 * 4) * 4u,
             g_gi + gi_row0 * G_ + (size_t)o_of0 * 4);
        if (ch1 < 60)
            cp16(gib_base + (unsigned)(b_of1 * G_ + o_of1 * 4) * 4u,
                 g_gi + gi_row1 * G_ + (size_t)o_of1 * 4);
        asm volatile("cp.async.commit_group;");
    }

    const float* ghw = sm + K2_GH + wid * 2 * PRS2;   // this warp's 2 rows

    for (int t = 0; t < T_; ++t) {
        // prefetch t+1 into buf (t+1)&1
        if (t + 1 < T_) {
            unsigned dst = gib_base + (unsigned)(((t + 1) & 1) * 240) * 4u;
            cp16(dst + (unsigned)(b_of0 * G_ + o_of0 * 4) * 4u,
                 g_gi + (gi_row0 + (t + 1)) * G_ + (size_t)o_of0 * 4);
            if (ch1 < 60)
                cp16(dst + (unsigned)(b_of1 * G_ + o_of1 * 4) * 4u,
                     g_gi + (gi_row1 + (t + 1)) * G_ + (size_t)o_of1 * 4);
        }
        asm volatile("cp.async.commit_group;");
        asm volatile("cp.async.wait_group 1;");
        __syncwarp();

        // ---- hidden projection: 2 batches x 128 gate cols ----
        u64 a0[2], a1[2];
        a0[0] = bH0; a0[1] = bH0; a1[0] = bH1; a1[1] = bH1;
        const float* hrow = sm + K2_H + wid * 2;
        #pragma unroll 8
        for (int k = 0; k < H_; ++k) {
            u64 w0 = *(const u64*)(wH + k * GP);
            u64 w1 = *(const u64*)(wH + k * GP + 64);
            float2 hv = *(const float2*)(hrow + k * HS2);
            u64 d0 = dup2(hv.x), d1 = dup2(hv.y);
            a0[0] = fma2(w0, d0, a0[0]); a1[0] = fma2(w1, d0, a1[0]);
            a0[1] = fma2(w0, d1, a0[1]); a1[1] = fma2(w1, d1, a1[1]);
        }
        float* pg0 = sm + K2_GH + (wid * 2) * PRS2 + 2 * gt;
        float* pg1 = pg0 + PRS2;
        *(u64*)pg0 = a0[0]; *(u64*)(pg0 + 64) = a1[0];
        *(u64*)pg1 = a0[1]; *(u64*)(pg1 + 64) = a1[1];
        __syncwarp();

        // ---- combine: 2 batches x 40 h = 80 items over 32 lanes ----
        const float* gib = sm + K2_GIB + wid * 480 + (t & 1) * 240;
        #pragma unroll
        for (int q = 0; q < 3; ++q) {
            if (q < 2 || gt < 16) {
                int item = gt + 32 * q;
                int b  = item & 1;
                int hh = item >> 1;
                const float* gi = gib + b * G_;
                const float* gh = ghw + b * PRS2;
                float rg = sigf(gi[hh]      + gh[hh]);
                float zg = sigf(gi[40 + hh] + gh[40 + hh]);
                float ng = tanh_fast(gi[80 + hh] + rg * gh[80 + hh]);
                float* hp = sm + K2_H + hh * HS2 + wid * 2 + b;
                float ho = *hp;
                *hp = ng + zg * (ho - ng);
            }
        }
        __syncwarp();
    }

    __syncthreads();
    if (tid < K2_BN) {
        float acc = bfc[c];
        #pragma unroll
        for (int h2 = 0; h2 < H_; ++h2)
            acc += sm[K2_H + h2 * HS2 + tid] * Wfc[c * H_ + h2];
        out[(size_t)(b0 + tid) * C_ + c] = sigf(acc);
    }
}

extern "C" void kernel_launch(void* const* d_in, const int* in_sizes, int n_in,
                              void* d_out, int out_size)
{
    const float* x   = (const float*)d_in[0];
    const float* Wih = (const float*)d_in[1];
    const float* Whh = (const float*)d_in[2];
    const float* bih = (const float*)d_in[3];
    const float* bhh = (const float*)d_in[4];
    const float* Wfc = (const float*)d_in[5];
    const float* bfc = (const float*)d_in[6];
    float* out = (float*)d_out;

    const int sm1 = K1_TOT * (int)sizeof(float);   // 49152
    const int sm2 = K2_TOT * (int)sizeof(float);   // 33984
    cudaFuncSetAttribute(gi_gemm_kernel,
                         cudaFuncAttributeMaxDynamicSharedMemorySize, sm1);
    cudaFuncSetAttribute(gru_rec_kernel,
                         cudaFuncAttributeMaxDynamicSharedMemorySize, sm2);

    gi_gemm_kernel<<<256, 128, sm1>>>(x, Wih, bih);
    gru_rec_kernel<<<512, 128, sm2>>>(Whh, bhh, Wfc, bfc, out);
}

// round 7
// speedup vs baseline: 1.1262x; 1.1262x over previous
#include <cuda_runtime.h>
#include <math.h>

#define C_   16
#define I_   64
#define H_   40
#define T_   512
#define G_   120
#define GP   128
#define TCH  4

typedef unsigned long long u64;

// 1 GB scratch: gi[b][c][t][g], rows of 120 floats (b_ih folded in)
__device__ float g_gi[(size_t)256 * 16 * 512 * 120];

__device__ __forceinline__ u64 pack2(float lo, float hi) {
    u64 r;
    asm("mov.b64 %0, {%1, %2};"
        : "=l"(r) : "r"(__float_as_uint(lo)), "r"(__float_as_uint(hi)));
    return r;
}
__device__ __forceinline__ u64 dup2(float v) {
    u64 r;
    asm("mov.b64 %0, {%1, %1};" : "=l"(r) : "r"(__float_as_uint(v)));
    return r;
}
__device__ __forceinline__ u64 fma2(u64 a, u64 b, u64 c) {
    u64 d;
    asm("fma.rn.f32x2 %0, %1, %2, %3;" : "=l"(d) : "l"(a), "l"(b), "l"(c));
    return d;
}
__device__ __forceinline__ float sigf(float v) {
    return __fdividef(1.0f, 1.0f + __expf(-v));
}
__device__ __forceinline__ float tanh_fast(float a) {
    a = fminf(fmaxf(a, -15.0f), 15.0f);
    float e = __expf(2.0f * a);
    return __fdividef(e - 1.0f, e + 1.0f);
}

// ============================================================================
// Kernel 1: gi[b,c,t,:] = W_ih[c] . x[b,c,:,t] + b_ih[c]
// grid 512 = (c, 8-batch), 128 thr, 4 CTAs/SM. Warp computes tt=wid x 8 batches.
// ============================================================================
#define K1_BN 8
#define K1_WIH 0                             // [64][128]
#define K1_X   (K1_WIH + I_ * GP)            // [4][64][8]
#define K1_TOT (K1_X + TCH * I_ * K1_BN)     // 10240 floats = 40960 B

__global__ void __launch_bounds__(128, 4)
gi_gemm_kernel(const float* __restrict__ x,
               const float* __restrict__ Wih,
               const float* __restrict__ bih)
{
    extern __shared__ float sm[];
    const int tid = threadIdx.x;
    const int c   = blockIdx.x & 15;
    const int b0  = (blockIdx.x >> 4) * K1_BN;

    for (int p = tid; p < I_ * GP; p += 128) {
        int k = p >> 7, g = p & 127;
        sm[K1_WIH + p] = (g < G_) ? Wih[(c * G_ + g) * I_ + k] : 0.0f;
    }
    __syncthreads();

    const int wid = tid >> 5;
    const int gt  = tid & 31;

    const int g0 = 2 * gt, g1 = 64 + 2 * gt;
    float bi1a = (g1     < G_) ? bih[c * G_ + g1]     : 0.0f;
    float bi1b = (g1 + 1 < G_) ? bih[c * G_ + g1 + 1] : 0.0f;
    const u64 bI0 = pack2(bih[c * G_ + g0], bih[c * G_ + g0 + 1]);
    const u64 bI1 = pack2(bi1a, bi1b);

    const float* wI = sm + K1_WIH + 2 * gt;

    const int lb  = tid & 7;       // staging: batch lane
    const int lig = tid >> 3;      // staging: i-group (0..15)
    const float* xg = x + ((size_t)(b0 + lb) * C_ + c) * (size_t)(I_ * T_);

    for (int tc = 0; tc < T_; tc += TCH) {
        __syncthreads();
        #pragma unroll
        for (int r = 0; r < 4; ++r) {
            int i = lig + (r << 4);
            float4 v = *(const float4*)(xg + i * T_ + tc);
            float* xp = sm + K1_X + i * 8 + lb;     // tt stride = 512
            xp[0] = v.x; xp[512] = v.y; xp[1024] = v.z; xp[1536] = v.w;
        }
        __syncthreads();

        // warp wid computes timestep tc+wid for 8 batches
        u64 a0[8], a1[8];
        #pragma unroll
        for (int b = 0; b < 8; ++b) { a0[b] = bI0; a1[b] = bI1; }
        const float* xr = sm + K1_X + wid * 512;
        #pragma unroll 8
        for (int k = 0; k < I_; ++k) {
            u64 w0 = *(const u64*)(wI + k * GP);
            u64 w1 = *(const u64*)(wI + k * GP + 64);
            const float* xk = xr + k * 8;
            float4 xa = *(const float4*)(xk);
            float4 xb = *(const float4*)(xk + 4);
            u64 d0 = dup2(xa.x), d1 = dup2(xa.y), d2 = dup2(xa.z), d3 = dup2(xa.w);
            u64 d4 = dup2(xb.x), d5 = dup2(xb.y), d6 = dup2(xb.z), d7 = dup2(xb.w);
            a0[0] = fma2(w0, d0, a0[0]); a1[0] = fma2(w1, d0, a1[0]);
            a0[1] = fma2(w0, d1, a0[1]); a1[1] = fma2(w1, d1, a1[1]);
            a0[2] = fma2(w0, d2, a0[2]); a1[2] = fma2(w1, d2, a1[2]);
            a0[3] = fma2(w0, d3, a0[3]); a1[3] = fma2(w1, d3, a1[3]);
            a0[4] = fma2(w0, d4, a0[4]); a1[4] = fma2(w1, d4, a1[4]);
            a0[5] = fma2(w0, d5, a0[5]); a1[5] = fma2(w1, d5, a1[5]);
            a0[6] = fma2(w0, d6, a0[6]); a1[6] = fma2(w1, d6, a1[6]);
            a0[7] = fma2(w0, d7, a0[7]); a1[7] = fma2(w1, d7, a1[7]);
        }
        const int t = tc + wid;
        #pragma unroll
        for (int b = 0; b < 8; ++b) {
            float* gp = g_gi + (((size_t)(b0 + b) * C_ + c) * T_ + t) * G_;
            *(u64*)(gp + 2 * gt) = a0[b];
            if (gt < 28) *(u64*)(gp + 64 + 2 * gt) = a1[b];
        }
    }
}

// ============================================================================
// Kernel 2: recurrence with W_hh in registers.
// grid 256 = (c, 16-batch), 128 thr, 2 CTAs/SM. Warp owns 4 batches, all gates.
// ============================================================================
#define K2_BN 16
#define HS2   20
#define PRS2  136
#define K2_WST 0                               // [40][128] staging (persists)
#define K2_H   (K2_WST + H_ * GP)              // [40][20]
#define K2_GH  (K2_H + H_ * HS2)               // [16][136]
#define K2_GIB (K2_GH + K2_BN * PRS2)          // [4 warps][2 buf][4 b][120]
#define K2_TOT (K2_GIB + 4 * 2 * 4 * G_)       // 11936 floats = 47744 B

__device__ __forceinline__ void cp16(unsigned smem_addr, const void* gptr) {
    asm volatile("cp.async.ca.shared.global [%0], [%1], 16;"
                 :: "r"(smem_addr), "l"(gptr));
}

__global__ void __launch_bounds__(128, 2)
gru_rec_kernel(const float* __restrict__ Whh,
               const float* __restrict__ bhh,
               const float* __restrict__ Wfc,
               const float* __restrict__ bfc,
               float* __restrict__ out)
{
    extern __shared__ float sm[];
    const int tid = threadIdx.x;
    const int c   = blockIdx.x & 15;
    const int b0  = (blockIdx.x >> 4) * K2_BN;

    // stage W_hh transposed [k][g], pad to 128
    for (int p = tid; p < H_ * GP; p += 128) {
        int k = p >> 7, g = p & 127;
        sm[K2_WST + p] = (g < G_) ? Whh[(c * G_ + g) * H_ + k] : 0.0f;
    }
    for (int p = tid; p < H_ * HS2; p += 128) sm[K2_H + p] = 0.0f;
    __syncthreads();

    const int wid = tid >> 5;
    const int gt  = tid & 31;
    const int bq  = wid * 4;       // this warp's batch quad

    // ---- pull W_hh into registers: 80 u64 per lane ----
    u64 w0r[H_], w1r[H_];
    #pragma unroll
    for (int k = 0; k < H_; ++k) {
        w0r[k] = *(const u64*)(sm + K2_WST + k * GP + 2 * gt);
        w1r[k] = *(const u64*)(sm + K2_WST + k * GP + 64 + 2 * gt);
    }

    const int g0 = 2 * gt, g1 = 64 + 2 * gt;
    float bh1a = (g1     < G_) ? bhh[c * G_ + g1]     : 0.0f;
    float bh1b = (g1 + 1 < G_) ? bhh[c * G_ + g1 + 1] : 0.0f;
    const u64 bH0 = pack2(bhh[c * G_ + g0], bhh[c * G_ + g0 + 1]);
    const u64 bH1 = pack2(bh1a, bh1b);

    // gi prefetch mapping: 4 batches x 30 16B-chunks = 120 chunks per warp
    const unsigned gib_base =
        (unsigned)__cvta_generic_to_shared(sm + K2_GIB + wid * 960);
    const int ch0 = gt,      b_of0 = ch0 / 30, o_of0 = ch0 % 30;
    const int ch1 = gt + 32, b_of1 = ch1 / 30, o_of1 = ch1 % 30;
    const int ch2 = gt + 64, b_of2 = ch2 / 30, o_of2 = ch2 % 30;
    const int ch3 = gt + 96, b_of3 = ch3 / 30, o_of3 = ch3 % 30;
    const size_t r0 = ((size_t)(b0 + bq + b_of0) * C_ + c) * T_;
    const size_t r1 = ((size_t)(b0 + bq + b_of1) * C_ + c) * T_;
    const size_t r2 = ((size_t)(b0 + bq + b_of2) * C_ + c) * T_;
    const size_t r3 = ((size_t)(b0 + bq + b_of3) * C_ + c) * T_;

    // prefetch t = 0 into buf 0
    {
        cp16(gib_base + (unsigned)(b_of0 * G_ + o_of0 * 4) * 4u,
             g_gi + r0 * G_ + (size_t)o_of0 * 4);
        cp16(gib_base + (unsigned)(b_of1 * G_ + o_of1 * 4) * 4u,
             g_gi + r1 * G_ + (size_t)o_of1 * 4);
        cp16(gib_base + (unsigned)(b_of2 * G_ + o_of2 * 4) * 4u,
             g_gi + r2 * G_ + (size_t)o_of2 * 4);
        if (ch3 < 120)
            cp16(gib_base + (unsigned)(b_of3 * G_ + o_of3 * 4) * 4u,
                 g_gi + r3 * G_ + (size_t)o_of3 * 4);
        asm volatile("cp.async.commit_group;");
    }

    // combine lane mapping: 4 batches x 40 h = 5 items/lane
    const int bl = bq + (gt >> 3);
    const int hb = gt & 7;

    for (int t = 0; t < T_; ++t) {
        if (t + 1 < T_) {
            unsigned dst = gib_base + (unsigned)(((t + 1) & 1) * 480) * 4u;
            cp16(dst + (unsigned)(b_of0 * G_ + o_of0 * 4) * 4u,
                 g_gi + (r0 + t + 1) * G_ + (size_t)o_of0 * 4);
            cp16(dst + (unsigned)(b_of1 * G_ + o_of1 * 4) * 4u,
                 g_gi + (r1 + t + 1) * G_ + (size_t)o_of1 * 4);
            cp16(dst + (unsigned)(b_of2 * G_ + o_of2 * 4) * 4u,
                 g_gi + (r2 + t + 1) * G_ + (size_t)o_of2 * 4);
            if (ch3 < 120)
                cp16(dst + (unsigned)(b_of3 * G_ + o_of3 * 4) * 4u,
                     g_gi + (r3 + t + 1) * G_ + (size_t)o_of3 * 4);
        }
        asm volatile("cp.async.commit_group;");
        asm volatile("cp.async.wait_group 1;");
        __syncwarp();

        // ---- hidden projection: registers x broadcast h ----
        u64 a0[4], a1[4];
        a0[0] = bH0; a0[1] = bH0; a0[2] = bH0; a0[3] = bH0;
        a1[0] = bH1; a1[1] = bH1; a1[2] = bH1; a1[3] = bH1;
        const float* hrow = sm + K2_H + bq;
        #pragma unroll
        for (int k = 0; k < H_; ++k) {
            float4 hv = *(const float4*)(hrow + k * HS2);
            u64 d0 = dup2(hv.x), d1 = dup2(hv.y), d2 = dup2(hv.z), d3 = dup2(hv.w);
            a0[0] = fma2(w0r[k], d0, a0[0]); a1[0] = fma2(w1r[k], d0, a1[0]);
            a0[1] = fma2(w0r[k], d1, a0[1]); a1[1] = fma2(w1r[k], d1, a1[1]);
            a0[2] = fma2(w0r[k], d2, a0[2]); a1[2] = fma2(w1r[k], d2, a1[2]);
            a0[3] = fma2(w0r[k], d3, a0[3]); a1[3] = fma2(w1r[k], d3, a1[3]);
        }
        // publish gh (warp-private rows)
        #pragma unroll
        for (int b = 0; b < 4; ++b) {
            float* pg = sm + K2_GH + (bq + b) * PRS2 + 2 * gt;
            *(u64*)pg        = a0[b];
            *(u64*)(pg + 64) = a1[b];
        }
        __syncwarp();

        // ---- combine + h update ----
        {
            const float* gi = sm + K2_GIB + wid * 960 + (t & 1) * 480
                              + (bl - bq) * G_;
            const float* gh = sm + K2_GH + bl * PRS2;
            #pragma unroll
            for (int q = 0; q < 5; ++q) {
                int hh = hb + 8 * q;
                float rg = sigf(gi[hh]      + gh[hh]);
                float zg = sigf(gi[40 + hh] + gh[40 + hh]);
                float ng = tanh_fast(gi[80 + hh] + rg * gh[80 + hh]);
                float* hp = sm + K2_H + hh * HS2 + bl;
                float ho = *hp;
                *hp = ng + zg * (ho - ng);
            }
        }
        __syncwarp();
    }

    __syncthreads();
    if (tid < K2_BN) {
        float acc = bfc[c];
        #pragma unroll
        for (int h2 = 0; h2 < H_; ++h2)
            acc += sm[K2_H + h2 * HS2 + tid] * Wfc[c * H_ + h2];
        out[(size_t)(b0 + tid) * C_ + c] = sigf(acc);
    }
}

extern "C" void kernel_launch(void* const* d_in, const int* in_sizes, int n_in,
                              void* d_out, int out_size)
{
    const float* x   = (const float*)d_in[0];
    const float* Wih = (const float*)d_in[1];
    const float* Whh = (const float*)d_in[2];
    const float* bih = (const float*)d_in[3];
    const float* bhh = (const float*)d_in[4];
    const float* Wfc = (const float*)d_in[5];
    const float* bfc = (const float*)d_in[6];
    float* out = (float*)d_out;

    const int sm1 = K1_TOT * (int)sizeof(float);   // 40960
    const int sm2 = K2_TOT * (int)sizeof(float);   // 47744
    cudaFuncSetAttribute(gi_gemm_kernel,
                         cudaFuncAttributeMaxDynamicSharedMemorySize, sm1);
    cudaFuncSetAttribute(gru_rec_kernel,
                         cudaFuncAttributeMaxDynamicSharedMemorySize, sm2);

    gi_gemm_kernel<<<512, 128, sm1>>>(x, Wih, bih);
    gru_rec_kernel<<<256, 128, sm2>>>(Whh, bhh, Wfc, bfc, out);
}

// round 8
// speedup vs baseline: 1.1921x; 1.0585x over previous
#include <cuda_runtime.h>
#include <math.h>

#define C_   16
#define I_   64
#define H_   40
#define T_   512
#define G_   120
#define GP   128

typedef unsigned long long u64;

// 1 GB scratch: gi[b][c][t][g], rows of 120 floats (b_ih folded in)
__device__ float g_gi[(size_t)256 * 16 * 512 * 120];

__device__ __forceinline__ u64 pack2(float lo, float hi) {
    u64 r;
    asm("mov.b64 %0, {%1, %2};"
        : "=l"(r) : "r"(__float_as_uint(lo)), "r"(__float_as_uint(hi)));
    return r;
}
__device__ __forceinline__ u64 dup2(float v) {
    u64 r;
    asm("mov.b64 %0, {%1, %1};" : "=l"(r) : "r"(__float_as_uint(v)));
    return r;
}
__device__ __forceinline__ u64 fma2(u64 a, u64 b, u64 c) {
    u64 d;
    asm("fma.rn.f32x2 %0, %1, %2, %3;" : "=l"(d) : "l"(a), "l"(b), "l"(c));
    return d;
}
__device__ __forceinline__ float sigf(float v) {
    return __fdividef(1.0f, 1.0f + __expf(-v));
}
__device__ __forceinline__ float tanh_fast(float a) {
    a = fminf(fmaxf(a, -15.0f), 15.0f);
    float e = __expf(2.0f * a);
    return __fdividef(e - 1.0f, e + 1.0f);
}

// ============================================================================
// Kernel 1: gi[b,c,t,:] = W_ih[c] . x[b,c,:,t] + b_ih[c]
// grid 256 = (c, 16-batch), 256 thr, 2 CTAs/SM (16 warps/SM), no spills.
// Warp computes timestep tt=wid for 16 batches; TCH=8.
// ============================================================================
#define K1_BN  16
#define K1_TCH 8
#define K1_WIH 0                               // [64][128]
#define K1_X   (K1_WIH + I_ * GP)              // [8][64][16]
#define K1_TOT (K1_X + K1_TCH * I_ * K1_BN)    // 16384 floats = 65536 B

__global__ void __launch_bounds__(256, 2)
gi_gemm_kernel(const float* __restrict__ x,
               const float* __restrict__ Wih,
               const float* __restrict__ bih)
{
    extern __shared__ float sm[];
    const int tid = threadIdx.x;
    const int c   = blockIdx.x & 15;
    const int b0  = (blockIdx.x >> 4) * K1_BN;

    for (int p = tid; p < I_ * GP; p += 256) {
        int k = p >> 7, g = p & 127;
        sm[K1_WIH + p] = (g < G_) ? Wih[(c * G_ + g) * I_ + k] : 0.0f;
    }
    __syncthreads();

    const int wid = tid >> 5;     // 0..7 -> timestep within chunk
    const int gt  = tid & 31;

    const int g0 = 2 * gt, g1 = 64 + 2 * gt;
    float bi1a = (g1     < G_) ? bih[c * G_ + g1]     : 0.0f;
    float bi1b = (g1 + 1 < G_) ? bih[c * G_ + g1 + 1] : 0.0f;
    const u64 bI0 = pack2(bih[c * G_ + g0], bih[c * G_ + g0 + 1]);
    const u64 bI1 = pack2(bi1a, bi1b);

    const float* wI = sm + K1_WIH + 2 * gt;

    // staging: lane pairs fill 32B sectors along t
    const int th  = tid & 1;             // t-half (0: t0..3, 1: t4..7)
    const int lb  = (tid >> 1) & 15;     // batch
    const int lig = tid >> 5;            // i-phase 0..7
    const float* xg = x + ((size_t)(b0 + lb) * C_ + c) * (size_t)(I_ * T_);

    for (int tc = 0; tc < T_; tc += K1_TCH) {
        __syncthreads();
        #pragma unroll
        for (int r = 0; r < 8; ++r) {
            int i = lig + (r << 3);
            float4 v = *(const float4*)(xg + i * T_ + tc + 4 * th);
            float* xp = sm + K1_X + i * 16 + lb;    // tt stride = 1024
            xp[(4 * th + 0) * 1024] = v.x;
            xp[(4 * th + 1) * 1024] = v.y;
            xp[(4 * th + 2) * 1024] = v.z;
            xp[(4 * th + 3) * 1024] = v.w;
        }
        __syncthreads();

        // warp wid computes timestep tc+wid for 16 batches
        u64 a0[16], a1[16];
        #pragma unroll
        for (int b = 0; b < 16; ++b) { a0[b] = bI0; a1[b] = bI1; }
        const float* xr = sm + K1_X + wid * 1024;
        #pragma unroll 2
        for (int k = 0; k < I_; ++k) {
            u64 w0 = *(const u64*)(wI + k * GP);
            u64 w1 = *(const u64*)(wI + k * GP + 64);
            const float* xk = xr + k * 16;
            float4 xa = *(const float4*)(xk);
            float4 xb = *(const float4*)(xk + 4);
            float4 xc = *(const float4*)(xk + 8);
            float4 xd = *(const float4*)(xk + 12);
            u64 d0 = dup2(xa.x), d1 = dup2(xa.y), d2 = dup2(xa.z), d3 = dup2(xa.w);
            u64 d4 = dup2(xb.x), d5 = dup2(xb.y), d6 = dup2(xb.z), d7 = dup2(xb.w);
            u64 d8 = dup2(xc.x), d9 = dup2(xc.y), da = dup2(xc.z), db = dup2(xc.w);
            u64 dc = dup2(xd.x), dd = dup2(xd.y), de = dup2(xd.z), df = dup2(xd.w);
            a0[0]  = fma2(w0, d0, a0[0]);  a1[0]  = fma2(w1, d0, a1[0]);
            a0[1]  = fma2(w0, d1, a0[1]);  a1[1]  = fma2(w1, d1, a1[1]);
            a0[2]  = fma2(w0, d2, a0[2]);  a1[2]  = fma2(w1, d2, a1[2]);
            a0[3]  = fma2(w0, d3, a0[3]);  a1[3]  = fma2(w1, d3, a1[3]);
            a0[4]  = fma2(w0, d4, a0[4]);  a1[4]  = fma2(w1, d4, a1[4]);
            a0[5]  = fma2(w0, d5, a0[5]);  a1[5]  = fma2(w1, d5, a1[5]);
            a0[6]  = fma2(w0, d6, a0[6]);  a1[6]  = fma2(w1, d6, a1[6]);
            a0[7]  = fma2(w0, d7, a0[7]);  a1[7]  = fma2(w1, d7, a1[7]);
            a0[8]  = fma2(w0, d8, a0[8]);  a1[8]  = fma2(w1, d8, a1[8]);
            a0[9]  = fma2(w0, d9, a0[9]);  a1[9]  = fma2(w1, d9, a1[9]);
            a0[10] = fma2(w0, da, a0[10]); a1[10] = fma2(w1, da, a1[10]);
            a0[11] = fma2(w0, db, a0[11]); a1[11] = fma2(w1, db, a1[11]);
            a0[12] = fma2(w0, dc, a0[12]); a1[12] = fma2(w1, dc, a1[12]);
            a0[13] = fma2(w0, dd, a0[13]); a1[13] = fma2(w1, dd, a1[13]);
            a0[14] = fma2(w0, de, a0[14]); a1[14] = fma2(w1, de, a1[14]);
            a0[15] = fma2(w0, df, a0[15]); a1[15] = fma2(w1, df, a1[15]);
        }
        const int t = tc + wid;
        #pragma unroll
        for (int b = 0; b < 16; ++b) {
            float* gp = g_gi + (((size_t)(b0 + b) * C_ + c) * T_ + t) * G_;
            *(u64*)(gp + 2 * gt) = a0[b];
            if (gt < 28) *(u64*)(gp + 64 + 2 * gt) = a1[b];
        }
    }
}

// ============================================================================
// Kernel 2: recurrence, W_hh in registers, batch-pair software pipeline.
// grid 256 = (c, 16-batch), 128 thr, 2 CTAs/SM. Warp owns 4 batches.
// ============================================================================
#define K2_BN 16
#define HS2   20
#define PRS2  136
#define K2_WST 0                               // [40][128] staging
#define K2_H   (K2_WST + H_ * GP)              // [40][20]
#define K2_GH  (K2_H + H_ * HS2)               // [16][136]
#define K2_GIB (K2_GH + K2_BN * PRS2)          // [4 warps][2 buf][4 b][120]
#define K2_TOT (K2_GIB + 4 * 2 * 4 * G_)       // 11936 floats = 47744 B

__device__ __forceinline__ void cp16(unsigned smem_addr, const void* gptr) {
    asm volatile("cp.async.ca.shared.global [%0], [%1], 16;"
                 :: "r"(smem_addr), "l"(gptr));
}

__global__ void __launch_bounds__(128, 2)
gru_rec_kernel(const float* __restrict__ Whh,
               const float* __restrict__ bhh,
               const float* __restrict__ Wfc,
               const float* __restrict__ bfc,
               float* __restrict__ out)
{
    extern __shared__ float sm[];
    const int tid = threadIdx.x;
    const int c   = blockIdx.x & 15;
    const int b0  = (blockIdx.x >> 4) * K2_BN;

    for (int p = tid; p < H_ * GP; p += 128) {
        int k = p >> 7, g = p & 127;
        sm[K2_WST + p] = (g < G_) ? Whh[(c * G_ + g) * H_ + k] : 0.0f;
    }
    for (int p = tid; p < H_ * HS2; p += 128) sm[K2_H + p] = 0.0f;
    __syncthreads();

    const int wid = tid >> 5;
    const int gt  = tid & 31;
    const int bq  = wid * 4;

    // W_hh in registers: 80 u64 per lane
    u64 w0r[H_], w1r[H_];
    #pragma unroll
    for (int k = 0; k < H_; ++k) {
        w0r[k] = *(const u64*)(sm + K2_WST + k * GP + 2 * gt);
        w1r[k] = *(const u64*)(sm + K2_WST + k * GP + 64 + 2 * gt);
    }

    const int g0 = 2 * gt, g1 = 64 + 2 * gt;
    float bh1a = (g1     < G_) ? bhh[c * G_ + g1]     : 0.0f;
    float bh1b = (g1 + 1 < G_) ? bhh[c * G_ + g1 + 1] : 0.0f;
    const u64 bH0 = pack2(bhh[c * G_ + g0], bhh[c * G_ + g0 + 1]);
    const u64 bH1 = pack2(bh1a, bh1b);

    // gi prefetch mapping: 4 batches x 30 16B-chunks per warp
    const unsigned gib_base =
        (unsigned)__cvta_generic_to_shared(sm + K2_GIB + wid * 960);
    const int ch0 = gt,      b_of0 = ch0 / 30, o_of0 = ch0 % 30;
    const int ch1 = gt + 32, b_of1 = ch1 / 30, o_of1 = ch1 % 30;
    const int ch2 = gt + 64, b_of2 = ch2 / 30, o_of2 = ch2 % 30;
    const int ch3 = gt + 96, b_of3 = ch3 / 30, o_of3 = ch3 % 30;
    const size_t r0 = ((size_t)(b0 + bq + b_of0) * C_ + c) * T_;
    const size_t r1 = ((size_t)(b0 + bq + b_of1) * C_ + c) * T_;
    const size_t r2 = ((size_t)(b0 + bq + b_of2) * C_ + c) * T_;
    const size_t r3 = ((size_t)(b0 + bq + b_of3) * C_ + c) * T_;

    // prefetch t = 0 into buf 0
    cp16(gib_base + (unsigned)(b_of0 * G_ + o_of0 * 4) * 4u,
         g_gi + r0 * G_ + (size_t)o_of0 * 4);
    cp16(gib_base + (unsigned)(b_of1 * G_ + o_of1 * 4) * 4u,
         g_gi + r1 * G_ + (size_t)o_of1 * 4);
    cp16(gib_base + (unsigned)(b_of2 * G_ + o_of2 * 4) * 4u,
         g_gi + r2 * G_ + (size_t)o_of2 * 4);
    if (ch3 < 120)
        cp16(gib_base + (unsigned)(b_of3 * G_ + o_of3 * 4) * 4u,
             g_gi + r3 * G_ + (size_t)o_of3 * 4);
    asm volatile("cp.async.commit_group;");

    // combine lane mapping within a batch pair
    const int cb  = gt & 1;       // batch within pair
    const int chh = gt >> 1;      // hh base 0..15

    for (int t = 0; t < T_; ++t) {
        if (t + 1 < T_) {
            unsigned dst = gib_base + (unsigned)(((t + 1) & 1) * 480) * 4u;
            cp16(dst + (unsigned)(b_of0 * G_ + o_of0 * 4) * 4u,
                 g_gi + (r0 + t + 1) * G_ + (size_t)o_of0 * 4);
            cp16(dst + (unsigned)(b_of1 * G_ + o_of1 * 4) * 4u,
                 g_gi + (r1 + t + 1) * G_ + (size_t)o_of1 * 4);
            cp16(dst + (unsigned)(b_of2 * G_ + o_of2 * 4) * 4u,
                 g_gi + (r2 + t + 1) * G_ + (size_t)o_of2 * 4);
            if (ch3 < 120)
                cp16(dst + (unsigned)(b_of3 * G_ + o_of3 * 4) * 4u,
                     g_gi + (r3 + t + 1) * G_ + (size_t)o_of3 * 4);
        }
        asm volatile("cp.async.commit_group;");
        asm volatile("cp.async.wait_group 1;");
        __syncwarp();

        const float* gibuf = sm + K2_GIB + wid * 960 + (t & 1) * 480;

        // ---- proj pair A (batches bq, bq+1) ----
        u64 aA0[2], aA1[2];
        aA0[0] = bH0; aA0[1] = bH0; aA1[0] = bH1; aA1[1] = bH1;
        {
            const float* hrow = sm + K2_H + bq;
            #pragma unroll
            for (int k = 0; k < H_; ++k) {
                float2 hv = *(const float2*)(hrow + k * HS2);
                u64 d0 = dup2(hv.x), d1 = dup2(hv.y);
                aA0[0] = fma2(w0r[k], d0, aA0[0]); aA1[0] = fma2(w1r[k], d0, aA1[0]);
                aA0[1] = fma2(w0r[k], d1, aA0[1]); aA1[1] = fma2(w1r[k], d1, aA1[1]);
            }
        }
        #pragma unroll
        for (int b = 0; b < 2; ++b) {
            float* pg = sm + K2_GH + (bq + b) * PRS2 + 2 * gt;
            *(u64*)pg        = aA0[b];
            *(u64*)(pg + 64) = aA1[b];
        }
        __syncwarp();

        // ---- proj pair B (batches bq+2, bq+3)  ||  combine pair A ----
        u64 aB0[2], aB1[2];
        aB0[0] = bH0; aB0[1] = bH0; aB1[0] = bH1; aB1[1] = bH1;
        {
            const float* hrow = sm + K2_H + bq + 2;
            #pragma unroll
            for (int k = 0; k < H_; ++k) {
                float2 hv = *(const float2*)(hrow + k * HS2);
                u64 d0 = dup2(hv.x), d1 = dup2(hv.y);
                aB0[0] = fma2(w0r[k], d0, aB0[0]); aB1[0] = fma2(w1r[k], d0, aB1[0]);
                aB0[1] = fma2(w0r[k], d1, aB0[1]); aB1[1] = fma2(w1r[k], d1, aB1[1]);
            }
        }
        // combine pair A (independent of proj B -> ILP overlap)
        {
            const int bl = bq + cb;
            const float* gi = gibuf + cb * G_;
            const float* gh = sm + K2_GH + bl * PRS2;
            #pragma unroll
            for (int q = 0; q < 2; ++q) {
                int hh = chh + 16 * q;
                float rg = sigf(gi[hh]      + gh[hh]);
                float zg = sigf(gi[40 + hh] + gh[40 + hh]);
                float ng = tanh_fast(gi[80 + hh] + rg * gh[80 + hh]);
                float* hp = sm + K2_H + hh * HS2 + bl;
                float ho = *hp;
                *hp = ng + zg * (ho - ng);
            }
            if (gt < 16) {
                int hh = chh + 32;
                float rg = sigf(gi[hh]      + gh[hh]);
                float zg = sigf(gi[40 + hh] + gh[40 + hh]);
                float ng = tanh_fast(gi[80 + hh] + rg * gh[80 + hh]);
                float* hp = sm + K2_H + hh * HS2 + bl;
                float ho = *hp;
                *hp = ng + zg * (ho - ng);
            }
        }
        #pragma unroll
        for (int b = 0; b < 2; ++b) {
            float* pg = sm + K2_GH + (bq + 2 + b) * PRS2 + 2 * gt;
            *(u64*)pg        = aB0[b];
            *(u64*)(pg + 64) = aB1[b];
        }
        __syncwarp();

        // ---- combine pair B ----
        {
            const int bl = bq + 2 + cb;
            const float* gi = gibuf + (2 + cb) * G_;
            const float* gh = sm + K2_GH + bl * PRS2;
            #pragma unroll
            for (int q = 0; q < 2; ++q) {
                int hh = chh + 16 * q;
                float rg = sigf(gi[hh]      + gh[hh]);
                float zg = sigf(gi[40 + hh] + gh[40 + hh]);
                float ng = tanh_fast(gi[80 + hh] + rg * gh[80 + hh]);
                float* hp = sm + K2_H + hh * HS2 + bl;
                float ho = *hp;
                *hp = ng + zg * (ho - ng);
            }
            if (gt < 16) {
                int hh = chh + 32;
                float rg = sigf(gi[hh]      + gh[hh]);
                float zg = sigf(gi[40 + hh] + gh[40 + hh]);
                float ng = tanh_fast(gi[80 + hh] + rg * gh[80 + hh]);
                float* hp = sm + K2_H + hh * HS2 + bl;
                float ho = *hp;
                *hp = ng + zg * (ho - ng);
            }
        }
        __syncwarp();
    }

    __syncthreads();
    if (tid < K2_BN) {
        float acc = bfc[c];
        #pragma unroll
        for (int h2 = 0; h2 < H_; ++h2)
            acc += sm[K2_H + h2 * HS2 + tid] * Wfc[c * H_ + h2];
        out[(size_t)(b0 + tid) * C_ + c] = sigf(acc);
    }
}

extern "C" void kernel_launch(void* const* d_in, const int* in_sizes, int n_in,
                              void* d_out, int out_size)
{
    const float* x   = (const float*)d_in[0];
    const float* Wih = (const float*)d_in[1];
    const float* Whh = (const float*)d_in[2];
    const float* bih = (const float*)d_in[3];
    const float* bhh = (const float*)d_in[4];
    const float* Wfc = (const float*)d_in[5];
    const float* bfc = (const float*)d_in[6];
    float* out = (float*)d_out;

    const int sm1 = K1_TOT * (int)sizeof(float);   // 65536
    const int sm2 = K2_TOT * (int)sizeof(float);   // 47744
    cudaFuncSetAttribute(gi_gemm_kernel,
                         cudaFuncAttributeMaxDynamicSharedMemorySize, sm1);
    cudaFuncSetAttribute(gru_rec_kernel,
                         cudaFuncAttributeMaxDynamicSharedMemorySize, sm2);

    gi_gemm_kernel<<<256, 256, sm1>>>(x, Wih, bih);
    gru_rec_kernel<<<256, 128, sm2>>>(Whh, bhh, Wfc, bfc, out);
}

// round 10
// speedup vs baseline: 1.2463x; 1.0454x over previous
#include <cuda_runtime.h>
#include <math.h>

#define C_   16
#define I_   64
#define H_   40
#define T_   512
#define G_   120
#define GP   128

typedef unsigned long long u64;

// 1 GB scratch: gi[b][c][t][g], rows of 120 floats (b_ih folded in)
__device__ float g_gi[(size_t)256 * 16 * 512 * 120];

__device__ __forceinline__ u64 pack2(float lo, float hi) {
    u64 r;
    asm("mov.b64 %0, {%1, %2};"
        : "=l"(r) : "r"(__float_as_uint(lo)), "r"(__float_as_uint(hi)));
    return r;
}
__device__ __forceinline__ u64 dup2(float v) {
    u64 r;
    asm("mov.b64 %0, {%1, %1};" : "=l"(r) : "r"(__float_as_uint(v)));
    return r;
}
__device__ __forceinline__ u64 fma2(u64 a, u64 b, u64 c) {
    u64 d;
    asm("fma.rn.f32x2 %0, %1, %2, %3;" : "=l"(d) : "l"(a), "l"(b), "l"(c));
    return d;
}
__device__ __forceinline__ float sigf(float v) {
    return __fdividef(1.0f, 1.0f + __expf(-v));
}
__device__ __forceinline__ float tanh_fast(float a) {
    a = fminf(fmaxf(a, -15.0f), 15.0f);
    float e = __expf(2.0f * a);
    return __fdividef(e - 1.0f, e + 1.0f);
}

// ============================================================================
// Kernel 1: gi = W_ih . x + b_ih  (unchanged from R7; measured ~960us)
// grid 256 = (c, 16-batch), 256 thr, 2 CTAs/SM.
// ============================================================================
#define K1_BN  16
#define K1_TCH 8
#define K1_WIH 0                               // [64][128]
#define K1_X   (K1_WIH + I_ * GP)              // [8][64][16]
#define K1_TOT (K1_X + K1_TCH * I_ * K1_BN)    // 16384 floats = 65536 B

__global__ void __launch_bounds__(256, 2)
gi_gemm_kernel(const float* __restrict__ x,
               const float* __restrict__ Wih,
               const float* __restrict__ bih)
{
    extern __shared__ float sm[];
    const int tid = threadIdx.x;
    const int c   = blockIdx.x & 15;
    const int b0  = (blockIdx.x >> 4) * K1_BN;

    for (int p = tid; p < I_ * GP; p += 256) {
        int k = p >> 7, g = p & 127;
        sm[K1_WIH + p] = (g < G_) ? Wih[(c * G_ + g) * I_ + k] : 0.0f;
    }
    __syncthreads();

    const int wid = tid >> 5;
    const int gt  = tid & 31;

    const int g0 = 2 * gt, g1 = 64 + 2 * gt;
    float bi1a = (g1     < G_) ? bih[c * G_ + g1]     : 0.0f;
    float bi1b = (g1 + 1 < G_) ? bih[c * G_ + g1 + 1] : 0.0f;
    const u64 bI0 = pack2(bih[c * G_ + g0], bih[c * G_ + g0 + 1]);
    const u64 bI1 = pack2(bi1a, bi1b);

    const float* wI = sm + K1_WIH + 2 * gt;

    const int th  = tid & 1;
    const int lb  = (tid >> 1) & 15;
    const int lig = tid >> 5;
    const float* xg = x + ((size_t)(b0 + lb) * C_ + c) * (size_t)(I_ * T_);

    for (int tc = 0; tc < T_; tc += K1_TCH) {
        __syncthreads();
        #pragma unroll
        for (int r = 0; r < 8; ++r) {
            int i = lig + (r << 3);
            float4 v = *(const float4*)(xg + i * T_ + tc + 4 * th);
            float* xp = sm + K1_X + i * 16 + lb;
            xp[(4 * th + 0) * 1024] = v.x;
            xp[(4 * th + 1) * 1024] = v.y;
            xp[(4 * th + 2) * 1024] = v.z;
            xp[(4 * th + 3) * 1024] = v.w;
        }
        __syncthreads();

        u64 a0[16], a1[16];
        #pragma unroll
        for (int b = 0; b < 16; ++b) { a0[b] = bI0; a1[b] = bI1; }
        const float* xr = sm + K1_X + wid * 1024;
        #pragma unroll 2
        for (int k = 0; k < I_; ++k) {
            u64 w0 = *(const u64*)(wI + k * GP);
            u64 w1 = *(const u64*)(wI + k * GP + 64);
            const float* xk = xr + k * 16;
            float4 xa = *(const float4*)(xk);
            float4 xb = *(const float4*)(xk + 4);
            float4 xc = *(const float4*)(xk + 8);
            float4 xd = *(const float4*)(xk + 12);
            u64 d0 = dup2(xa.x), d1 = dup2(xa.y), d2 = dup2(xa.z), d3 = dup2(xa.w);
            u64 d4 = dup2(xb.x), d5 = dup2(xb.y), d6 = dup2(xb.z), d7 = dup2(xb.w);
            u64 d8 = dup2(xc.x), d9 = dup2(xc.y), da = dup2(xc.z), db = dup2(xc.w);
            u64 dc = dup2(xd.x), dd = dup2(xd.y), de = dup2(xd.z), df = dup2(xd.w);
            a0[0]  = fma2(w0, d0, a0[0]);  a1[0]  = fma2(w1, d0, a1[0]);
            a0[1]  = fma2(w0, d1, a0[1]);  a1[1]  = fma2(w1, d1, a1[1]);
            a0[2]  = fma2(w0, d2, a0[2]);  a1[2]  = fma2(w1, d2, a1[2]);
            a0[3]  = fma2(w0, d3, a0[3]);  a1[3]  = fma2(w1, d3, a1[3]);
            a0[4]  = fma2(w0, d4, a0[4]);  a1[4]  = fma2(w1, d4, a1[4]);
            a0[5]  = fma2(w0, d5, a0[5]);  a1[5]  = fma2(w1, d5, a1[5]);
            a0[6]  = fma2(w0, d6, a0[6]);  a1[6]  = fma2(w1, d6, a1[6]);
            a0[7]  = fma2(w0, d7, a0[7]);  a1[7]  = fma2(w1, d7, a1[7]);
            a0[8]  = fma2(w0, d8, a0[8]);  a1[8]  = fma2(w1, d8, a1[8]);
            a0[9]  = fma2(w0, d9, a0[9]);  a1[9]  = fma2(w1, d9, a1[9]);
            a0[10] = fma2(w0, da, a0[10]); a1[10] = fma2(w1, da, a1[10]);
            a0[11] = fma2(w0, db, a0[11]); a1[11] = fma2(w1, db, a1[11]);
            a0[12] = fma2(w0, dc, a0[12]); a1[12] = fma2(w1, dc, a1[12]);
            a0[13] = fma2(w0, dd, a0[13]); a1[13] = fma2(w1, dd, a1[13]);
            a0[14] = fma2(w0, de, a0[14]); a1[14] = fma2(w1, de, a1[14]);
            a0[15] = fma2(w0, df, a0[15]); a1[15] = fma2(w1, df, a1[15]);
        }
        const int t = tc + wid;
        #pragma unroll
        for (int b = 0; b < 16; ++b) {
            float* gp = g_gi + (((size_t)(b0 + b) * C_ + c) * T_ + t) * G_;
            *(u64*)(gp + 2 * gt) = a0[b];
            if (gt < 28) *(u64*)(gp + 64 + 2 * gt) = a1[b];
        }
    }
}

// ============================================================================
// Kernel 2: recurrence, k-split warp pairs. 256 thr, 2 CTAs/SM (16 warps/SM).
// Warp pair owns 4 batches; each warp holds half of W_hh (k-range) in regs.
// ============================================================================
#define K2_BN 16
#define HS2   20
#define PRS2  136
#define KH    20     // k per half
#define K2_WST 0                               // [40][128]
#define K2_H   (K2_WST + H_ * GP)              // [40][20]
#define K2_GH  (K2_H + H_ * HS2)               // [2 halves][16][136]
#define K2_GIB (K2_GH + 2 * K2_BN * PRS2)      // [4 pairs][2 buf][4 b][120]
#define K2_TOT (K2_GIB + 4 * 2 * 4 * G_)       // 14112 floats = 56448 B

__device__ __forceinline__ void cp16(unsigned smem_addr, const void* gptr) {
    asm volatile("cp.async.ca.shared.global [%0], [%1], 16;"
                 :: "r"(smem_addr), "l"(gptr));
}

__global__ void __launch_bounds__(256, 2)
gru_rec_kernel(const float* __restrict__ Whh,
               const float* __restrict__ bhh,
               const float* __restrict__ Wfc,
               const float* __restrict__ bfc,
               float* __restrict__ out)
{
    extern __shared__ float sm[];
    const int tid = threadIdx.x;
    const int c   = blockIdx.x & 15;
    const int b0  = (blockIdx.x >> 4) * K2_BN;

    for (int p = tid; p < H_ * GP; p += 256) {
        int k = p >> 7, g = p & 127;
        sm[K2_WST + p] = (g < G_) ? Whh[(c * G_ + g) * H_ + k] : 0.0f;
    }
    for (int p = tid; p < H_ * HS2; p += 256) sm[K2_H + p] = 0.0f;
    __syncthreads();

    const int wid  = tid >> 5;
    const int gt   = tid & 31;
    const int pair = wid >> 1;       // 0..3
    const int half = wid & 1;        // k half
    const int bq   = pair * 4;       // pair's batch quad
    const int barid = 1 + pair;

    // ---- this half's W_hh in registers: 40 u64 per lane ----
    u64 w0r[KH], w1r[KH];
    #pragma unroll
    for (int kk = 0; kk < KH; ++kk) {
        int k = half * KH + kk;
        w0r[kk] = *(const u64*)(sm + K2_WST + k * GP + 2 * gt);
        w1r[kk] = *(const u64*)(sm + K2_WST + k * GP + 64 + 2 * gt);
    }

    // bias only in half 0's partial
    const int g0 = 2 * gt, g1 = 64 + 2 * gt;
    u64 bH0 = 0ull, bH1 = 0ull;
    if (half == 0) {
        float b1a = (g1     < G_) ? bhh[c * G_ + g1]     : 0.0f;
        float b1b = (g1 + 1 < G_) ? bhh[c * G_ + g1 + 1] : 0.0f;
        bH0 = pack2(bhh[c * G_ + g0], bhh[c * G_ + g0 + 1]);
        bH1 = pack2(b1a, b1b);
    }

    // gi prefetch: warp covers its 2 batches (mb, mb+1): 60 x 16B chunks
    const int mb = bq + 2 * half;
    const unsigned gib_pair =
        (unsigned)__cvta_generic_to_shared(sm + K2_GIB + pair * 960);
    const int ch0 = gt,      b_of0 = ch0 / 30, o_of0 = ch0 % 30;
    const int ch1 = gt + 32, b_of1 = ch1 / 30, o_of1 = ch1 % 30;
    const size_t r0 = ((size_t)(b0 + mb + b_of0) * C_ + c) * T_;
    const size_t r1 = ((size_t)(b0 + mb + b_of1) * C_ + c) * T_;
    const unsigned d0off = (unsigned)((2 * half + b_of0) * G_ + o_of0 * 4) * 4u;
    const unsigned d1off = (unsigned)((2 * half + b_of1) * G_ + o_of1 * 4) * 4u;

    cp16(gib_pair + d0off, g_gi + r0 * G_ + (size_t)o_of0 * 4);
    if (ch1 < 60)
        cp16(gib_pair + d1off, g_gi + r1 * G_ + (size_t)o_of1 * 4);
    asm volatile("cp.async.commit_group;");

    // combine mapping: 64 lanes of the pair cover 160 items (b, hh)
    const int lp  = half * 32 + gt;      // 0..63
    const int cb  = lp & 3;              // batch in quad
    const int hh0 = lp >> 2;             // 0..15

    float* ghA = sm + K2_GH + (bq + cb) * PRS2;            // half-0 partial
    float* ghB = ghA + K2_BN * PRS2;                        // half-1 partial
    float* myGH = sm + K2_GH + half * (K2_BN * PRS2);

    for (int t = 0; t < T_; ++t) {
        if (t + 1 < T_) {
            unsigned dst = gib_pair + (unsigned)(((t + 1) & 1) * 480) * 4u;
            cp16(dst + d0off, g_gi + (r0 + t + 1) * G_ + (size_t)o_of0 * 4);
            if (ch1 < 60)
                cp16(dst + d1off, g_gi + (r1 + t + 1) * G_ + (size_t)o_of1 * 4);
        }
        asm volatile("cp.async.commit_group;");
        asm volatile("cp.async.wait_group 1;");

        // ---- partial hidden projection over this half's k-range ----
        u64 a0[4], a1[4];
        a0[0] = bH0; a0[1] = bH0; a0[2] = bH0; a0[3] = bH0;
        a1[0] = bH1; a1[1] = bH1; a1[2] = bH1; a1[3] = bH1;
        const float* hrow = sm + K2_H + half * KH * HS2 + bq;
        #pragma unroll
        for (int kk = 0; kk < KH; ++kk) {
            float4 hv = *(const float4*)(hrow + kk * HS2);
            u64 d0 = dup2(hv.x), d1 = dup2(hv.y), d2 = dup2(hv.z), d3 = dup2(hv.w);
            a0[0] = fma2(w0r[kk], d0, a0[0]); a1[0] = fma2(w1r[kk], d0, a1[0]);
            a0[1] = fma2(w0r[kk], d1, a0[1]); a1[1] = fma2(w1r[kk], d1, a1[1]);
            a0[2] = fma2(w0r[kk], d2, a0[2]); a1[2] = fma2(w1r[kk], d2, a1[2]);
            a0[3] = fma2(w0r[kk], d3, a0[3]); a1[3] = fma2(w1r[kk], d3, a1[3]);
        }
        #pragma unroll
        for (int b = 0; b < 4; ++b) {
            float* pg = myGH + (bq + b) * PRS2 + 2 * gt;
            *(u64*)pg        = a0[b];
            *(u64*)(pg + 64) = a1[b];
        }
        asm volatile("bar.sync %0, 64;" :: "r"(barid) : "memory");

        // ---- combine: items (cb, hh0), (cb, hh0+16), (cb, hh0+32 if lp<32) ----
        {
            const float* gi = sm + K2_GIB + pair * 960 + (t & 1) * 480 + cb * G_;
            #pragma unroll
            for (int q = 0; q < 2; ++q) {
                int hh = hh0 + 16 * q;
                float rg = sigf(gi[hh]      + ghA[hh]      + ghB[hh]);
                float zg = sigf(gi[40 + hh] + ghA[40 + hh] + ghB[40 + hh]);
                float ng = tanh_fast(gi[80 + hh]
                                     + rg * (ghA[80 + hh] + ghB[80 + hh]));
                float* hp = sm + K2_H + hh * HS2 + bq + cb;
                float ho = *hp;
                *hp = ng + zg * (ho - ng);
            }
            if (lp < 32) {
                int hh = hh0 + 32;
                float rg = sigf(gi[hh]      + ghA[hh]      + ghB[hh]);
                float zg = sigf(gi[40 + hh] + ghA[40 + hh] + ghB[40 + hh]);
                float ng = tanh_fast(gi[80 + hh]
                                     + rg * (ghA[80 + hh] + ghB[80 + hh]));
                float* hp = sm + K2_H + hh * HS2 + bq + cb;
                float ho = *hp;
                *hp = ng + zg * (ho - ng);
            }
        }
        asm volatile("bar.sync %0, 64;" :: "r"(barid) : "memory");
    }

    __syncthreads();
    if (tid < K2_BN) {
        float acc = bfc[c];
        #pragma unroll
        for (int h2 = 0; h2 < H_; ++h2)
            acc += sm[K2_H + h2 * HS2 + tid] * Wfc[c * H_ + h2];
        out[(size_t)(b0 + tid) * C_ + c] = sigf(acc);
    }
}

extern "C" void kernel_launch(void* const* d_in, const int* in_sizes, int n_in,
                              void* d_out, int out_size)
{
    const float* x   = (const float*)d_in[0];
    const float* Wih = (const float*)d_in[1];
    const float* Whh = (const float*)d_in[2];
    const float* bih = (const float*)d_in[3];
    const float* bhh = (const float*)d_in[4];
    const float* Wfc = (const float*)d_in[5];
    const float* bfc = (const float*)d_in[6];
    float* out = (float*)d_out;

    const int sm1 = K1_TOT * (int)sizeof(float);   // 65536
    const int sm2 = K2_TOT * (int)sizeof(float);   // 56448
    cudaFuncSetAttribute(gi_gemm_kernel,
                         cudaFuncAttributeMaxDynamicSharedMemorySize, sm1);
    cudaFuncSetAttribute(gru_rec_kernel,
                         cudaFuncAttributeMaxDynamicSharedMemorySize, sm2);

    gi_gemm_kernel<<<256, 256, sm1>>>(x, Wih, bih);
    gru_rec_kernel<<<256, 256, sm2>>>(Whh, bhh, Wfc, bfc, out);
}